// round 13
// baseline (speedup 1.0000x reference)
#include <cuda_runtime.h>
#include <cstdint>

#define NV     8192
#define NT     1000
#define UNITS  20
#define IND    12
#define NCOL   80
#define VB     16           // vehicles per block
#define XSTR   36           // padded xin stride (floats): 144B -> 4-bank shift/vehicle
#define THREADS 160         // 4 groups of 40 threads; group serves 4 vehicles
#define BLOCKS (NV/VB)      // 512; 5 blocks/SM -> one wave

// output packing (flat concat in reference return order)
#define OUT_POS 0
#define OUT_LC  (NV*NT)
#define OUT_SPD (OUT_LC + NV*NT*3)
#define OUT_H   (OUT_SPD + NV)
#define OUT_C   (OUT_H + NV*UNITS)

typedef unsigned long long ull;

__device__ __forceinline__ ull pk(float x, float y) {
    ull r; asm("mov.b64 %0, {%1,%2};" : "=l"(r) : "f"(x), "f"(y)); return r;
}
__device__ __forceinline__ float2 unpk(ull v) {
    float2 f; asm("mov.b64 {%0,%1}, %2;" : "=f"(f.x), "=f"(f.y) : "l"(v)); return f;
}
__device__ __forceinline__ void ffma2(ull& d, ull a, ull b) {
    asm("fma.rn.f32x2 %0, %1, %2, %0;" : "+l"(d) : "l"(a), "l"(b));
}
__device__ __forceinline__ ull add2(ull a, ull b) {
    ull r; asm("add.rn.f32x2 %0, %1, %2;" : "=l"(r) : "l"(a), "l"(b)); return r;
}
__device__ __forceinline__ void lds2u64(ull& a, ull& b, uint32_t addr) {
    asm volatile("ld.shared.v2.u64 {%0,%1}, [%2];" : "=l"(a), "=l"(b) : "r"(addr));
}
__device__ __forceinline__ ull lds64(uint32_t addr) {
    ull r; asm volatile("ld.shared.b64 %0, [%1];" : "=l"(r) : "r"(addr)); return r;
}
__device__ __forceinline__ float tanhap(float x) {   // MUFU.TANH, 1 op
    float r; asm("tanh.approx.f32 %0, %1;" : "=f"(r) : "f"(x)); return r;
}
__device__ __forceinline__ float sig_ap(float x) {   // sigmoid via tanh: 1 MUFU + 1 FMA
    return fmaf(0.5f, tanhap(0.5f * x), 0.5f);
}
__device__ __forceinline__ float nanfix(float v) { return (v == v) ? v : 1.0f; }

__device__ __forceinline__ void cpasync16(uint32_t dst, const void* src) {
    asm volatile("cp.async.cg.shared.global [%0], [%1], 16;" :: "r"(dst), "l"(src));
}
#define CP_COMMIT() asm volatile("cp.async.commit_group;")
#define CP_WAIT0()  asm volatile("cp.async.wait_group 0;")

__global__ void __launch_bounds__(THREADS, 5)
rnncf_kernel(const float* __restrict__ inp,        // (NV, NT, 12)
             const float* __restrict__ init_state, // (NV, 2)
             const float* __restrict__ h0,         // (NV, 20)
             const float* __restrict__ c0,         // (NV, 20)
             const float* __restrict__ Wk,         // (12, 80)
             const float* __restrict__ Wr,         // (20, 80)
             const float* __restrict__ bz,         // (80)
             const float* __restrict__ d2w,        // (20, 10)
             const float* __restrict__ d2b,        // (10)
             const float* __restrict__ lcw,        // (10, 3)
             const float* __restrict__ lcb,        // (3)
             const float* __restrict__ d1w,        // (10, 1)
             const float* __restrict__ d1b,        // (1)
             float* __restrict__ out)
{
    // xin[buf][v][0..11]=cur, [12..31]=h, [32..35]=pad (bank de-conflict)
    __shared__ __align__(16) float xin[2][VB][XSTR];
    __shared__ __align__(16) float raws[2][VB][12];
    __shared__ float xs[VB][12];
    __shared__ float s_spd[VB];
    __shared__ float s_pos[VB];
    __shared__ float s_c[VB][UNITS];      // cell state (demoted from regs for occ=5)
    __shared__ __align__(16) ull s_d2p[10][10];  // [q][xc] = (d2w[2q][xc], d2w[2q+1][xc])
    __shared__ float s_d2b[10];
    __shared__ float s_head[10][4];       // [m][q]: q<3 -> lcw col q, q=3 -> d1w
    __shared__ float s_headb[4];

    const int tid  = threadIdx.x;
    const int grpv = tid / 40;          // group 0..3, serves 4 vehicles
    const int r    = tid % 40;
    const int u    = r >> 1;            // unit 0..19
    const int p    = r & 1;             // 0 -> (i,f) columns, 1 -> (g,o) columns
    const int v0   = grpv * 4;
    const int vbase0 = blockIdx.x * VB;
    const int xv = tid / 10, xc = tid % 10;   // Phase-B mapping (16 veh x 10 cols)

    // ---- static head weights -> smem ----
    if (tid < 100) {
        int q = tid / 10, c = tid % 10;
        s_d2p[q][c] = pk(d2w[(2 * q) * 10 + c], d2w[(2 * q + 1) * 10 + c]);
    }
    if (tid < 10) s_d2b[tid] = d2b[tid];
    if (tid < 40) { int m = tid >> 2, q = tid & 3; s_head[m][q] = (q < 3) ? lcw[m * 3 + q] : d1w[m]; }
    if (tid < 4)  s_headb[tid] = (tid < 3) ? lcb[tid] : d1b[0];

    // ---- branchless activation constants (for column A) ----
    // actA = fmaf(mA, tanhap(kA*z), cA):  p=0 -> sigmoid(z_i), p=1 -> tanh(z_g)
    const float kA = p ? 1.0f : 0.5f;
    const float mA = p ? 1.0f : 0.5f;
    const float cA = p ? 0.0f : 0.5f;

    // ---- register-resident weights: two columns, packed across k ----
    const int colA = p ? (40 + u) : u;          // g or i
    const int colB = p ? (60 + u) : (20 + u);   // o or f
    ull wA[16], wB[16];
#pragma unroll
    for (int q = 0; q < 16; q++) {
        int k0 = 2 * q, k1 = 2 * q + 1;
        float a0 = (k0 < IND) ? Wk[k0 * NCOL + colA] : Wr[(k0 - IND) * NCOL + colA];
        float a1 = (k1 < IND) ? Wk[k1 * NCOL + colA] : Wr[(k1 - IND) * NCOL + colA];
        wA[q] = pk(a0, a1);
        float b0 = (k0 < IND) ? Wk[k0 * NCOL + colB] : Wr[(k0 - IND) * NCOL + colB];
        float b1 = (k1 < IND) ? Wk[k1 * NCOL + colB] : Wr[(k1 - IND) * NCOL + colB];
        wB[q] = pk(b0, b1);
    }
    const float bzA = bz[colA], bzB = bz[colB];
    const ull zero2 = pk(0.0f, 0.0f);

    // ---- state init (cell state + h into smem) ----
    for (int i = tid; i < VB * UNITS; i += THREADS) {   // h0 -> xin[0], c0 -> s_c
        int v = i / UNITS, uu = i % UNITS;
        xin[0][v][12 + uu] = h0[(vbase0 + v) * UNITS + uu];
        s_c[v][uu] = c0[(vbase0 + v) * UNITS + uu];
    }
    if (tid < VB) {                     // owners concentrated in warp 0
        const int ov = tid;
        const int vg = vbase0 + ov;
        float pos = init_state[vg * 2 + 0];
        s_pos[ov] = pos;
        s_spd[ov] = init_state[vg * 2 + 1];
        const float4* ip = (const float4*)(inp + (size_t)vg * NT * 12);
        float4 r0 = ip[0], r1 = ip[1], r2 = ip[2];
        float* cb = &xin[0][ov][0];
        const float ih = 0.01f, iv = 0.025f;
        cb[0]  = nanfix((r0.x - pos) * ih);
        cb[1]  = nanfix((r0.y - pos) * ih);
        cb[2]  = nanfix((r0.z - pos) * ih);
        cb[3]  = nanfix((pos - r0.w) * ih);
        cb[4]  = nanfix((pos - r1.x) * ih);
        cb[5]  = nanfix((pos - r1.y) * ih);
        cb[6]  = nanfix(r1.z * iv);
        cb[7]  = nanfix(r1.w * iv);
        cb[8]  = nanfix(r2.x * iv);
        cb[9]  = nanfix(r2.y * iv);
        cb[10] = nanfix(r2.z * iv);
        cb[11] = nanfix(r2.w * iv);
        uint32_t d = (uint32_t)__cvta_generic_to_shared(&raws[1][ov][0]);
        const float* src = inp + ((size_t)vg * NT + 1) * 12;
        cpasync16(d, src); cpasync16(d + 16, src + 4); cpasync16(d + 32, src + 8);
        CP_COMMIT();
    }
    __syncthreads();

    for (int t = 0; t < NT; t++) {
        const int tb = t & 1;

        // ---- Phase A: LSTM matvec + gates + cell, 4 vehicles (all 160 thr) ----
#pragma unroll
        for (int vi = 0; vi < 4; vi++) {
            const int v = v0 + vi;
            uint32_t xb = (uint32_t)__cvta_generic_to_shared(&xin[tb][v][0]);
            ull aA0 = pk(bzA, 0.0f), aA1 = zero2;
            ull aB0 = pk(bzB, 0.0f), aB1 = zero2;
#pragma unroll
            for (int q = 0; q < 8; q++) {       // 16B of x feeds 4 FFMA2
                ull xa, xc2;
                lds2u64(xa, xc2, xb + q * 16);
                ffma2(aA0, xa, wA[2 * q]);
                ffma2(aB0, xa, wB[2 * q]);
                ffma2(aA1, xc2, wA[2 * q + 1]);
                ffma2(aB1, xc2, wB[2 * q + 1]);
            }
            float2 fA = unpk(add2(aA0, aA1));
            float2 fB = unpk(add2(aB0, aB1));
            float zA = fA.x + fA.y;
            float zB = fB.x + fB.y;
            float actA = fmaf(mA, tanhap(kA * zA), cA);  // p0: sig(i); p1: tanh(g)
            float actB = sig_ap(zB);                     // p0: sig(f); p1: sig(o)
            float oa = __shfl_xor_sync(0xFFFFFFFFu, actA, 1);  // partner's A
            float ob = __shfl_xor_sync(0xFFFFFFFFu, actB, 1);  // partner's B
            if (p == 0) {   // p0 holds: si=actA, sf=actB, tg=oa, so=ob
                float cc = fmaf(actB, s_c[v][u], actA * oa);
                s_c[v][u] = cc;
                xin[tb ^ 1][v][12 + u] = ob * tanhap(cc);
            }
        }
        __syncthreads();   // barrier 1: h(t) visible

        // ---- Phase B: head-x in f32x2 (all 160 thr) + owner work (warp 0) ----
        {
            uint32_t hb = (uint32_t)__cvta_generic_to_shared(&xin[tb ^ 1][xv][12]);
            uint32_t wb = (uint32_t)__cvta_generic_to_shared(&s_d2p[0][xc]);
            ull a0 = pk(s_d2b[xc], 0.0f), a1 = zero2;
#pragma unroll
            for (int m = 0; m < 5; m++) {       // h pairs feed FFMA2 directly
                ull ha, hc;
                lds2u64(ha, hc, hb + m * 16);
                ffma2(a0, ha, lds64(wb + (2 * m) * 80));
                ffma2(a1, hc, lds64(wb + (2 * m + 1) * 80));
            }
            float2 f = unpk(add2(a0, a1));
            xs[xv][xc] = fmaxf(f.x + f.y, 0.0f);
        }
        if (tid < VB) {
            const int ov = tid;
            const int vg = vbase0 + ov;
            CP_WAIT0();                        // raw(t+1) landed
            float spd = s_spd[ov];             // spd(t): C(t) updates only after bar2
            float pos = fmaf(0.1f, spd, s_pos[ov]);  // pos(t+1) = reference pos at t
            s_pos[ov] = pos;
            out[OUT_POS + (size_t)vg * NT + t] = pos;
            const float4* rw = (const float4*)&raws[(t + 1) & 1][ov][0];
            float4 r0 = rw[0], r1 = rw[1], r2 = rw[2];
            float* cb = &xin[tb ^ 1][ov][0];   // cur floats [0..11]
            const float ih = 0.01f, iv = 0.025f;
            cb[0]  = nanfix((r0.x - pos) * ih);
            cb[1]  = nanfix((r0.y - pos) * ih);
            cb[2]  = nanfix((r0.z - pos) * ih);
            cb[3]  = nanfix((pos - r0.w) * ih);
            cb[4]  = nanfix((pos - r1.x) * ih);
            cb[5]  = nanfix((pos - r1.y) * ih);
            cb[6]  = nanfix(r1.z * iv);
            cb[7]  = nanfix(r1.w * iv);
            cb[8]  = nanfix(r2.x * iv);
            cb[9]  = nanfix(r2.y * iv);
            cb[10] = nanfix(r2.z * iv);
            cb[11] = nanfix(r2.w * iv);
            if (t + 2 < NT) {                  // prefetch raw(t+2)
                uint32_t d = (uint32_t)__cvta_generic_to_shared(&raws[t & 1][ov][0]);
                const float* src = inp + ((size_t)vg * NT + (t + 2)) * 12;
                cpasync16(d, src); cpasync16(d + 16, src + 4); cpasync16(d + 32, src + 8);
                CP_COMMIT();
            }
        }
        __syncthreads();   // barrier 2: xs + cur(t+1) visible

        // ---- Phase C: lc / acc / spd (warps 0-1; no trailing barrier) ----
        if (tid < 4 * VB) {
            const int cv = tid >> 2, cq = tid & 3;
            const int vg = vbase0 + cv;
            float acc = s_headb[cq];
#pragma unroll
            for (int m = 0; m < 10; m++) acc = fmaf(xs[cv][m], s_head[m][cq], acc);
            if (cq < 3) {
                out[OUT_LC + ((size_t)vg * NT + t) * 3 + cq] = acc;
            } else {
                float a = fmaf(10.0f, acc, -6.0f);
                s_spd[cv] = fmaf(0.1f, a, s_spd[cv]);
            }
        }
        // C(t) reads xs / writes s_spd; B(t+1) writes xs / reads s_spd — ordered
        // by barrier 1 of step t+1. A(t+1) touches only xin buffers, disjoint.
    }

    __syncthreads();
    // ---- finals ----
    if (tid < VB) out[OUT_SPD + vbase0 + tid] = s_spd[tid];
    for (int i = tid; i < VB * UNITS; i += THREADS) {
        int v = i / UNITS, uu = i % UNITS;
        out[OUT_H + (size_t)(vbase0 + v) * UNITS + uu] = xin[NT & 1][v][12 + uu];
        out[OUT_C + (size_t)(vbase0 + v) * UNITS + uu] = s_c[v][uu];
    }
}

extern "C" void kernel_launch(void* const* d_in, const int* in_sizes, int n_in,
                              void* d_out, int out_size) {
    const float* inp        = (const float*)d_in[0];
    const float* init_state = (const float*)d_in[1];
    const float* h0         = (const float*)d_in[2];
    const float* c0         = (const float*)d_in[3];
    const float* Wk         = (const float*)d_in[4];
    const float* Wr         = (const float*)d_in[5];
    const float* bzv        = (const float*)d_in[6];
    const float* d2w        = (const float*)d_in[7];
    const float* d2b        = (const float*)d_in[8];
    const float* lcw        = (const float*)d_in[9];
    const float* lcb        = (const float*)d_in[10];
    const float* d1w        = (const float*)d_in[11];
    const float* d1b        = (const float*)d_in[12];
    float* out = (float*)d_out;

    rnncf_kernel<<<BLOCKS, THREADS>>>(inp, init_state, h0, c0, Wk, Wr, bzv,
                                      d2w, d2b, lcw, lcb, d1w, d1b, out);
}

// round 14
// speedup vs baseline: 1.3353x; 1.3353x over previous
#include <cuda_runtime.h>
#include <cstdint>

#define NV     8192
#define NT     1000
#define UNITS  20
#define IND    12
#define NCOL   80
#define VB     16           // vehicles per block
#define XSTR   36           // padded xin stride (floats): 144B -> 4-bank shift/vehicle
#define THREADS 160         // 4 groups of 40 threads; group serves 4 vehicles
#define BLOCKS (NV/VB)      // 512  -> one residency wave

// output packing (flat concat in reference return order)
#define OUT_POS 0
#define OUT_LC  (NV*NT)
#define OUT_SPD (OUT_LC + NV*NT*3)
#define OUT_H   (OUT_SPD + NV)
#define OUT_C   (OUT_H + NV*UNITS)

typedef unsigned long long ull;

__device__ __forceinline__ ull pk(float x, float y) {
    ull r; asm("mov.b64 %0, {%1,%2};" : "=l"(r) : "f"(x), "f"(y)); return r;
}
__device__ __forceinline__ float2 unpk(ull v) {
    float2 f; asm("mov.b64 {%0,%1}, %2;" : "=f"(f.x), "=f"(f.y) : "l"(v)); return f;
}
__device__ __forceinline__ void ffma2(ull& d, ull a, ull b) {
    asm("fma.rn.f32x2 %0, %1, %2, %0;" : "+l"(d) : "l"(a), "l"(b));
}
__device__ __forceinline__ ull add2(ull a, ull b) {
    ull r; asm("add.rn.f32x2 %0, %1, %2;" : "=l"(r) : "l"(a), "l"(b)); return r;
}
__device__ __forceinline__ void lds2u64(ull& a, ull& b, uint32_t addr) {
    asm volatile("ld.shared.v2.u64 {%0,%1}, [%2];" : "=l"(a), "=l"(b) : "r"(addr));
}
__device__ __forceinline__ ull lds64(uint32_t addr) {
    ull r; asm volatile("ld.shared.b64 %0, [%1];" : "=l"(r) : "r"(addr)); return r;
}
__device__ __forceinline__ float tanhap(float x) {   // MUFU.TANH, 1 op
    float r; asm("tanh.approx.f32 %0, %1;" : "=f"(r) : "f"(x)); return r;
}
__device__ __forceinline__ float sig_ap(float x) {   // sigmoid via tanh: 1 MUFU + 1 FMA
    return fmaf(0.5f, tanhap(0.5f * x), 0.5f);
}
__device__ __forceinline__ float nanfix(float v) { return (v == v) ? v : 1.0f; }

__device__ __forceinline__ void cpasync16(uint32_t dst, const void* src) {
    asm volatile("cp.async.cg.shared.global [%0], [%1], 16;" :: "r"(dst), "l"(src));
}
#define CP_COMMIT() asm volatile("cp.async.commit_group;")
#define CP_WAIT0()  asm volatile("cp.async.wait_group 0;")

__global__ void __launch_bounds__(THREADS, 4)
rnncf_kernel(const float* __restrict__ inp,        // (NV, NT, 12)
             const float* __restrict__ init_state, // (NV, 2)
             const float* __restrict__ h0,         // (NV, 20)
             const float* __restrict__ c0,         // (NV, 20)
             const float* __restrict__ Wk,         // (12, 80)
             const float* __restrict__ Wr,         // (20, 80)
             const float* __restrict__ bz,         // (80)
             const float* __restrict__ d2w,        // (20, 10)
             const float* __restrict__ d2b,        // (10)
             const float* __restrict__ lcw,        // (10, 3)
             const float* __restrict__ lcb,        // (3)
             const float* __restrict__ d1w,        // (10, 1)
             const float* __restrict__ d1b,        // (1)
             float* __restrict__ out)
{
    // xin[buf][v][0..11]=cur, [12..31]=h, [32..35]=pad (bank de-conflict)
    __shared__ __align__(16) float xin[2][VB][XSTR];
    __shared__ __align__(16) float raws[2][VB][12];
    __shared__ float xs[VB][12];
    __shared__ float s_spd[VB];
    __shared__ __align__(16) ull s_d2p[10][10];  // [q][xc] = (d2w[2q][xc], d2w[2q+1][xc])
    __shared__ float s_d2b[10];
    __shared__ float s_head[10][4];       // [m][q]: q<3 -> lcw col q, q=3 -> d1w
    __shared__ float s_headb[4];

    const int tid  = threadIdx.x;
    const int grpv = tid / 40;          // group 0..3, serves 4 vehicles
    const int r    = tid % 40;
    const int u    = r >> 1;            // unit 0..19
    const int p    = r & 1;             // 0 -> (i,f) columns, 1 -> (g,o) columns
    const int v0   = grpv * 4;
    const int vbase0 = blockIdx.x * VB;
    const int xv = tid / 10, xc = tid % 10;   // Phase-B mapping (16 veh x 10 cols)

    // ---- static head weights -> smem ----
    if (tid < 100) {
        int q = tid / 10, c = tid % 10;
        s_d2p[q][c] = pk(d2w[(2 * q) * 10 + c], d2w[(2 * q + 1) * 10 + c]);
    }
    if (tid < 10) s_d2b[tid] = d2b[tid];
    if (tid < 40) { int m = tid >> 2, q = tid & 3; s_head[m][q] = (q < 3) ? lcw[m * 3 + q] : d1w[m]; }
    if (tid < 4)  s_headb[tid] = (tid < 3) ? lcb[tid] : d1b[0];

    // ---- branchless activation constants (for column A) ----
    // actA = fmaf(mA, tanhap(kA*z), cA):  p=0 -> sigmoid(z_i), p=1 -> tanh(z_g)
    const float kA = p ? 1.0f : 0.5f;
    const float mA = p ? 1.0f : 0.5f;
    const float cA = p ? 0.0f : 0.5f;

    // ---- register-resident weights: two columns, packed across k ----
    const int colA = p ? (40 + u) : u;          // g or i
    const int colB = p ? (60 + u) : (20 + u);   // o or f
    ull wA[16], wB[16];
#pragma unroll
    for (int q = 0; q < 16; q++) {
        int k0 = 2 * q, k1 = 2 * q + 1;
        float a0 = (k0 < IND) ? Wk[k0 * NCOL + colA] : Wr[(k0 - IND) * NCOL + colA];
        float a1 = (k1 < IND) ? Wk[k1 * NCOL + colA] : Wr[(k1 - IND) * NCOL + colA];
        wA[q] = pk(a0, a1);
        float b0 = (k0 < IND) ? Wk[k0 * NCOL + colB] : Wr[(k0 - IND) * NCOL + colB];
        float b1 = (k1 < IND) ? Wk[k1 * NCOL + colB] : Wr[(k1 - IND) * NCOL + colB];
        wB[q] = pk(b0, b1);
    }
    const float bzA = bz[colA], bzB = bz[colB];
    const ull zero2 = pk(0.0f, 0.0f);

    // ---- state init ----
    float c2[4];
#pragma unroll
    for (int vi = 0; vi < 4; vi++)
        c2[vi] = c0[(vbase0 + v0 + vi) * UNITS + u];
    float pos = 0.0f;

    for (int i = tid; i < VB * UNITS; i += THREADS) {   // h0 -> xin[0]
        int v = i / UNITS, uu = i % UNITS;
        xin[0][v][12 + uu] = h0[(vbase0 + v) * UNITS + uu];
    }
    if (tid < VB) {                     // owners concentrated in warp 0
        const int ov = tid;
        const int vg = vbase0 + ov;
        pos = init_state[vg * 2 + 0];
        s_spd[ov] = init_state[vg * 2 + 1];
        const float4* ip = (const float4*)(inp + (size_t)vg * NT * 12);
        float4 r0 = ip[0], r1 = ip[1], r2 = ip[2];
        const float ih = 0.01f, iv = 0.025f;
        float4 f0, f1, f2;
        f0.x = nanfix((r0.x - pos) * ih);
        f0.y = nanfix((r0.y - pos) * ih);
        f0.z = nanfix((r0.z - pos) * ih);
        f0.w = nanfix((pos - r0.w) * ih);
        f1.x = nanfix((pos - r1.x) * ih);
        f1.y = nanfix((pos - r1.y) * ih);
        f1.z = nanfix(r1.z * iv);
        f1.w = nanfix(r1.w * iv);
        f2.x = nanfix(r2.x * iv);
        f2.y = nanfix(r2.y * iv);
        f2.z = nanfix(r2.z * iv);
        f2.w = nanfix(r2.w * iv);
        float4* cb4 = (float4*)&xin[0][ov][0];
        cb4[0] = f0; cb4[1] = f1; cb4[2] = f2;
        uint32_t d = (uint32_t)__cvta_generic_to_shared(&raws[1][ov][0]);
        const float* src = inp + ((size_t)vg * NT + 1) * 12;
        cpasync16(d, src); cpasync16(d + 16, src + 4); cpasync16(d + 32, src + 8);
        CP_COMMIT();
    }
    __syncthreads();

    for (int t = 0; t < NT; t++) {
        const int tb = t & 1;

        // ---- Phase A: LSTM matvec + gates + cell, 4 vehicles (all 160 thr) ----
#pragma unroll
        for (int vi = 0; vi < 4; vi++) {
            const int v = v0 + vi;
            uint32_t xb = (uint32_t)__cvta_generic_to_shared(&xin[tb][v][0]);
            ull aA0 = pk(bzA, 0.0f), aA1 = zero2;
            ull aB0 = pk(bzB, 0.0f), aB1 = zero2;
#pragma unroll
            for (int q = 0; q < 8; q++) {       // 16B of x feeds 4 FFMA2
                ull xa, xc2;
                lds2u64(xa, xc2, xb + q * 16);
                ffma2(aA0, xa, wA[2 * q]);
                ffma2(aB0, xa, wB[2 * q]);
                ffma2(aA1, xc2, wA[2 * q + 1]);
                ffma2(aB1, xc2, wB[2 * q + 1]);
            }
            float2 fA = unpk(add2(aA0, aA1));
            float2 fB = unpk(add2(aB0, aB1));
            float zA = fA.x + fA.y;
            float zB = fB.x + fB.y;
            float actA = fmaf(mA, tanhap(kA * zA), cA);  // p0: sig(i); p1: tanh(g)
            float actB = sig_ap(zB);                     // p0: sig(f); p1: sig(o)
            float oa = __shfl_xor_sync(0xFFFFFFFFu, actA, 1);  // partner's A
            float ob = __shfl_xor_sync(0xFFFFFFFFu, actB, 1);  // partner's B
            if (p == 0) {   // p0 holds: si=actA, sf=actB, tg=oa, so=ob
                float cc = fmaf(actB, c2[vi], actA * oa);
                c2[vi] = cc;
                xin[tb ^ 1][v][12 + u] = ob * tanhap(cc);
            }
        }
        __syncthreads();   // barrier 1: h(t) visible

        // ---- Phase B: head-x in f32x2 (all 160 thr) + owner work (warp 0) ----
        {
            uint32_t hb = (uint32_t)__cvta_generic_to_shared(&xin[tb ^ 1][xv][12]);
            uint32_t wb = (uint32_t)__cvta_generic_to_shared(&s_d2p[0][xc]);
            ull a0 = pk(s_d2b[xc], 0.0f), a1 = zero2;
#pragma unroll
            for (int m = 0; m < 5; m++) {       // h pairs feed FFMA2 directly
                ull ha, hc;
                lds2u64(ha, hc, hb + m * 16);
                ffma2(a0, ha, lds64(wb + (2 * m) * 80));
                ffma2(a1, hc, lds64(wb + (2 * m + 1) * 80));
            }
            float2 f = unpk(add2(a0, a1));
            xs[xv][xc] = fmaxf(f.x + f.y, 0.0f);
        }
        if (tid < VB) {
            const int ov = tid;
            const int vg = vbase0 + ov;
            CP_WAIT0();                        // raw(t+1) landed
            float spd = s_spd[ov];             // spd(t): C(t) updates only after bar2
            pos = fmaf(0.1f, spd, pos);        // pos(t+1) = reference pos output at t
            out[OUT_POS + (size_t)vg * NT + t] = pos;
            const float4* rw = (const float4*)&raws[(t + 1) & 1][ov][0];
            float4 r0 = rw[0], r1 = rw[1], r2 = rw[2];
            const float ih = 0.01f, iv = 0.025f;
            float4 f0, f1, f2;
            f0.x = nanfix((r0.x - pos) * ih);
            f0.y = nanfix((r0.y - pos) * ih);
            f0.z = nanfix((r0.z - pos) * ih);
            f0.w = nanfix((pos - r0.w) * ih);
            f1.x = nanfix((pos - r1.x) * ih);
            f1.y = nanfix((pos - r1.y) * ih);
            f1.z = nanfix(r1.z * iv);
            f1.w = nanfix(r1.w * iv);
            f2.x = nanfix(r2.x * iv);
            f2.y = nanfix(r2.y * iv);
            f2.z = nanfix(r2.z * iv);
            f2.w = nanfix(r2.w * iv);
            float4* cb4 = (float4*)&xin[tb ^ 1][ov][0];   // 16B-aligned (144*ov)
            cb4[0] = f0; cb4[1] = f1; cb4[2] = f2;        // 3x STS.128
            if (t + 2 < NT) {                  // prefetch raw(t+2)
                uint32_t d = (uint32_t)__cvta_generic_to_shared(&raws[t & 1][ov][0]);
                const float* src = inp + ((size_t)vg * NT + (t + 2)) * 12;
                cpasync16(d, src); cpasync16(d + 16, src + 4); cpasync16(d + 32, src + 8);
                CP_COMMIT();
            }
        }
        __syncthreads();   // barrier 2: xs + cur(t+1) visible

        // ---- Phase C: lc / acc / spd (warps 0-1; no trailing barrier) ----
        if (tid < 4 * VB) {
            const int cv = tid >> 2, cq = tid & 3;
            const int vg = vbase0 + cv;
            float acc = s_headb[cq];
#pragma unroll
            for (int m = 0; m < 10; m++) acc = fmaf(xs[cv][m], s_head[m][cq], acc);
            if (cq < 3) {
                out[OUT_LC + ((size_t)vg * NT + t) * 3 + cq] = acc;
            } else {
                float a = fmaf(10.0f, acc, -6.0f);
                s_spd[cv] = fmaf(0.1f, a, s_spd[cv]);
            }
        }
        // C(t) reads xs / writes s_spd; B(t+1) writes xs / reads s_spd — ordered
        // by barrier 1 of step t+1. A(t+1) touches only xin buffers, disjoint.
    }

    __syncthreads();
    // ---- finals ----
    if (tid < VB) out[OUT_SPD + vbase0 + tid] = s_spd[tid];
    for (int i = tid; i < VB * UNITS; i += THREADS) {
        int v = i / UNITS, uu = i % UNITS;
        out[OUT_H + (size_t)(vbase0 + v) * UNITS + uu] = xin[NT & 1][v][12 + uu];
    }
    if (p == 0) {
#pragma unroll
        for (int vi = 0; vi < 4; vi++)
            out[OUT_C + (size_t)(vbase0 + v0 + vi) * UNITS + u] = c2[vi];
    }
}

extern "C" void kernel_launch(void* const* d_in, const int* in_sizes, int n_in,
                              void* d_out, int out_size) {
    const float* inp        = (const float*)d_in[0];
    const float* init_state = (const float*)d_in[1];
    const float* h0         = (const float*)d_in[2];
    const float* c0         = (const float*)d_in[3];
    const float* Wk         = (const float*)d_in[4];
    const float* Wr         = (const float*)d_in[5];
    const float* bzv        = (const float*)d_in[6];
    const float* d2w        = (const float*)d_in[7];
    const float* d2b        = (const float*)d_in[8];
    const float* lcw        = (const float*)d_in[9];
    const float* lcb        = (const float*)d_in[10];
    const float* d1w        = (const float*)d_in[11];
    const float* d1b        = (const float*)d_in[12];
    float* out = (float*)d_out;

    rnncf_kernel<<<BLOCKS, THREADS>>>(inp, init_state, h0, c0, Wk, Wr, bzv,
                                      d2w, d2b, lcw, lcb, d1w, d1b, out);
}

// round 15
// speedup vs baseline: 2.0993x; 1.5722x over previous
#include <cuda_runtime.h>
#include <cstdint>

#define NV     8192
#define NT     1000
#define UNITS  20
#define IND    12
#define NCOL   80
#define VB     16           // vehicles per block
#define XSTR   36           // padded xin stride (floats): 144B -> 4-bank shift/vehicle
#define THREADS 160         // 4 groups of 40 threads; group serves 4 vehicles
#define BLOCKS (NV/VB)      // 512  -> one residency wave

// output packing (flat concat in reference return order)
#define OUT_POS 0
#define OUT_LC  (NV*NT)
#define OUT_SPD (OUT_LC + NV*NT*3)
#define OUT_H   (OUT_SPD + NV)
#define OUT_C   (OUT_H + NV*UNITS)

typedef unsigned long long ull;

__device__ __forceinline__ ull pk(float x, float y) {
    ull r; asm("mov.b64 %0, {%1,%2};" : "=l"(r) : "f"(x), "f"(y)); return r;
}
__device__ __forceinline__ float2 unpk(ull v) {
    float2 f; asm("mov.b64 {%0,%1}, %2;" : "=f"(f.x), "=f"(f.y) : "l"(v)); return f;
}
__device__ __forceinline__ void ffma2(ull& d, ull a, ull b) {
    asm("fma.rn.f32x2 %0, %1, %2, %0;" : "+l"(d) : "l"(a), "l"(b));
}
__device__ __forceinline__ ull add2(ull a, ull b) {
    ull r; asm("add.rn.f32x2 %0, %1, %2;" : "=l"(r) : "l"(a), "l"(b)); return r;
}
__device__ __forceinline__ void lds2u64(ull& a, ull& b, uint32_t addr) {
    asm volatile("ld.shared.v2.u64 {%0,%1}, [%2];" : "=l"(a), "=l"(b) : "r"(addr));
}
__device__ __forceinline__ ull lds64(uint32_t addr) {
    ull r; asm volatile("ld.shared.b64 %0, [%1];" : "=l"(r) : "r"(addr)); return r;
}
__device__ __forceinline__ float tanhap(float x) {   // MUFU.TANH, 1 op
    float r; asm("tanh.approx.f32 %0, %1;" : "=f"(r) : "f"(x)); return r;
}
__device__ __forceinline__ float sig_ap(float x) {   // sigmoid via tanh: 1 MUFU + 1 FMA
    return fmaf(0.5f, tanhap(0.5f * x), 0.5f);
}
__device__ __forceinline__ float nanfix(float v) { return (v == v) ? v : 1.0f; }

__device__ __forceinline__ void cpasync16(uint32_t dst, const void* src) {
    asm volatile("cp.async.cg.shared.global [%0], [%1], 16;" :: "r"(dst), "l"(src));
}
#define CP_COMMIT() asm volatile("cp.async.commit_group;")
#define CP_WAIT0()  asm volatile("cp.async.wait_group 0;")

__global__ void __launch_bounds__(THREADS, 4)
rnncf_kernel(const float* __restrict__ inp,        // (NV, NT, 12)
             const float* __restrict__ init_state, // (NV, 2)
             const float* __restrict__ h0,         // (NV, 20)
             const float* __restrict__ c0,         // (NV, 20)
             const float* __restrict__ Wk,         // (12, 80)
             const float* __restrict__ Wr,         // (20, 80)
             const float* __restrict__ bz,         // (80)
             const float* __restrict__ d2w,        // (20, 10)
             const float* __restrict__ d2b,        // (10)
             const float* __restrict__ lcw,        // (10, 3)
             const float* __restrict__ lcb,        // (3)
             const float* __restrict__ d1w,        // (10, 1)
             const float* __restrict__ d1b,        // (1)
             float* __restrict__ out)
{
    // xin[buf][v][0..11]=cur, [12..31]=h, [32..35]=pad (bank de-conflict)
    __shared__ __align__(16) float xin[2][VB][XSTR];
    __shared__ __align__(16) float raws[2][VB][12];
    __shared__ float xs[VB][12];
    __shared__ float s_spd[VB];
    __shared__ __align__(16) ull s_d2p[10][10];  // [q][xc] = (d2w[2q][xc], d2w[2q+1][xc])
    __shared__ float s_d2b[10];
    __shared__ float s_head[10][4];       // [m][q]: q<3 -> lcw col q, q=3 -> d1w
    __shared__ float s_headb[4];

    const int tid  = threadIdx.x;
    const int grpv = tid / 40;          // group 0..3, serves 4 vehicles
    const int r    = tid % 40;
    const int u    = r >> 1;            // unit 0..19
    const int p    = r & 1;             // 0 -> (i,f) columns, 1 -> (g,o) columns
    const int v0   = grpv * 4;
    const int vbase0 = blockIdx.x * VB;
    const int xv = tid / 10, xc = tid % 10;   // Phase-B mapping (16 veh x 10 cols)

    // ---- static head weights -> smem ----
    if (tid < 100) {
        int q = tid / 10, c = tid % 10;
        s_d2p[q][c] = pk(d2w[(2 * q) * 10 + c], d2w[(2 * q + 1) * 10 + c]);
    }
    if (tid < 10) s_d2b[tid] = d2b[tid];
    if (tid < 40) { int m = tid >> 2, q = tid & 3; s_head[m][q] = (q < 3) ? lcw[m * 3 + q] : d1w[m]; }
    if (tid < 4)  s_headb[tid] = (tid < 3) ? lcb[tid] : d1b[0];

    // ---- branchless activation constants (for column A) ----
    // actA = fmaf(mA, tanhap(kA*z), cA):  p=0 -> sigmoid(z_i), p=1 -> tanh(z_g)
    const float kA = p ? 1.0f : 0.5f;
    const float mA = p ? 1.0f : 0.5f;
    const float cA = p ? 0.0f : 0.5f;

    // ---- register-resident weights: two columns, packed across k ----
    const int colA = p ? (40 + u) : u;          // g or i
    const int colB = p ? (60 + u) : (20 + u);   // o or f
    ull wA[16], wB[16];
#pragma unroll
    for (int q = 0; q < 16; q++) {
        int k0 = 2 * q, k1 = 2 * q + 1;
        float a0 = (k0 < IND) ? Wk[k0 * NCOL + colA] : Wr[(k0 - IND) * NCOL + colA];
        float a1 = (k1 < IND) ? Wk[k1 * NCOL + colA] : Wr[(k1 - IND) * NCOL + colA];
        wA[q] = pk(a0, a1);
        float b0 = (k0 < IND) ? Wk[k0 * NCOL + colB] : Wr[(k0 - IND) * NCOL + colB];
        float b1 = (k1 < IND) ? Wk[k1 * NCOL + colB] : Wr[(k1 - IND) * NCOL + colB];
        wB[q] = pk(b0, b1);
    }
    const float bzA = bz[colA], bzB = bz[colB];
    const ull zero2 = pk(0.0f, 0.0f);

    // ---- state init ----
    float c2[4];
#pragma unroll
    for (int vi = 0; vi < 4; vi++)
        c2[vi] = c0[(vbase0 + v0 + vi) * UNITS + u];
    float pos = 0.0f;

    for (int i = tid; i < VB * UNITS; i += THREADS) {   // h0 -> xin[0]
        int v = i / UNITS, uu = i % UNITS;
        xin[0][v][12 + uu] = h0[(vbase0 + v) * UNITS + uu];
    }
    if (tid < VB) {                     // owners concentrated in warp 0
        const int ov = tid;
        const int vg = vbase0 + ov;
        pos = init_state[vg * 2 + 0];
        s_spd[ov] = init_state[vg * 2 + 1];
        const float4* ip = (const float4*)(inp + (size_t)vg * NT * 12);
        float4 r0 = ip[0], r1 = ip[1], r2 = ip[2];
        const float ih = 0.01f, iv = 0.025f;
        float4 f0, f1, f2;
        f0.x = nanfix((r0.x - pos) * ih);
        f0.y = nanfix((r0.y - pos) * ih);
        f0.z = nanfix((r0.z - pos) * ih);
        f0.w = nanfix((pos - r0.w) * ih);
        f1.x = nanfix((pos - r1.x) * ih);
        f1.y = nanfix((pos - r1.y) * ih);
        f1.z = nanfix(r1.z * iv);
        f1.w = nanfix(r1.w * iv);
        f2.x = nanfix(r2.x * iv);
        f2.y = nanfix(r2.y * iv);
        f2.z = nanfix(r2.z * iv);
        f2.w = nanfix(r2.w * iv);
        float4* cb4 = (float4*)&xin[0][ov][0];
        cb4[0] = f0; cb4[1] = f1; cb4[2] = f2;
        uint32_t d = (uint32_t)__cvta_generic_to_shared(&raws[1][ov][0]);
        const float* src = inp + ((size_t)vg * NT + 1) * 12;
        cpasync16(d, src); cpasync16(d + 16, src + 4); cpasync16(d + 32, src + 8);
        CP_COMMIT();
    }
    __syncthreads();

    for (int t = 0; t < NT; t++) {
        const int tb = t & 1;

        // ---- Phase A: LSTM matvec + gates + cell, 4 vehicles (all 160 thr) ----
#pragma unroll
        for (int vi = 0; vi < 4; vi++) {
            const int v = v0 + vi;
            uint32_t xb = (uint32_t)__cvta_generic_to_shared(&xin[tb][v][0]);
            ull aA0 = pk(bzA, 0.0f), aA1 = zero2;
            ull aB0 = pk(bzB, 0.0f), aB1 = zero2;
#pragma unroll
            for (int q = 0; q < 8; q++) {       // 16B of x feeds 4 FFMA2
                ull xa, xc2;
                lds2u64(xa, xc2, xb + q * 16);
                ffma2(aA0, xa, wA[2 * q]);
                ffma2(aB0, xa, wB[2 * q]);
                ffma2(aA1, xc2, wA[2 * q + 1]);
                ffma2(aB1, xc2, wB[2 * q + 1]);
            }
            float2 fA = unpk(add2(aA0, aA1));
            float2 fB = unpk(add2(aB0, aB1));
            float zA = fA.x + fA.y;
            float zB = fB.x + fB.y;
            float actA = fmaf(mA, tanhap(kA * zA), cA);  // p0: sig(i); p1: tanh(g)
            float actB = sig_ap(zB);                     // p0: sig(f); p1: sig(o)
            float oa = __shfl_xor_sync(0xFFFFFFFFu, actA, 1);  // partner's A
            float ob = __shfl_xor_sync(0xFFFFFFFFu, actB, 1);  // partner's B
            if (p == 0) {   // p0 holds: si=actA, sf=actB, tg=oa, so=ob
                float cc = fmaf(actB, c2[vi], actA * oa);
                c2[vi] = cc;
                xin[tb ^ 1][v][12 + u] = ob * tanhap(cc);
            }
        }
        __syncthreads();   // barrier 1: h(t) visible

        // ---- Phase B: head-x in f32x2 (all 160 thr) + owner work (warp 0) ----
        {
            uint32_t hb = (uint32_t)__cvta_generic_to_shared(&xin[tb ^ 1][xv][12]);
            uint32_t wb = (uint32_t)__cvta_generic_to_shared(&s_d2p[0][xc]);
            ull a0 = pk(s_d2b[xc], 0.0f), a1 = zero2;
#pragma unroll
            for (int m = 0; m < 5; m++) {       // h pairs feed FFMA2 directly
                ull ha, hc;
                lds2u64(ha, hc, hb + m * 16);
                ffma2(a0, ha, lds64(wb + (2 * m) * 80));
                ffma2(a1, hc, lds64(wb + (2 * m + 1) * 80));
            }
            float2 f = unpk(add2(a0, a1));
            xs[xv][xc] = fmaxf(f.x + f.y, 0.0f);
        }
        if (tid < VB) {
            const int ov = tid;
            const int vg = vbase0 + ov;
            CP_WAIT0();                        // raw(t+1) landed
            float spd = s_spd[ov];             // spd(t): C(t) updates only after bar2
            pos = fmaf(0.1f, spd, pos);        // pos(t+1) = reference pos output at t
            out[OUT_POS + (size_t)vg * NT + t] = pos;
            const float4* rw = (const float4*)&raws[(t + 1) & 1][ov][0];
            float4 r0 = rw[0], r1 = rw[1], r2 = rw[2];
            const float ih = 0.01f, iv = 0.025f;
            float4 f0, f1, f2;
            f0.x = nanfix((r0.x - pos) * ih);
            f0.y = nanfix((r0.y - pos) * ih);
            f0.z = nanfix((r0.z - pos) * ih);
            f0.w = nanfix((pos - r0.w) * ih);
            f1.x = nanfix((pos - r1.x) * ih);
            f1.y = nanfix((pos - r1.y) * ih);
            f1.z = nanfix(r1.z * iv);
            f1.w = nanfix(r1.w * iv);
            f2.x = nanfix(r2.x * iv);
            f2.y = nanfix(r2.y * iv);
            f2.z = nanfix(r2.z * iv);
            f2.w = nanfix(r2.w * iv);
            float4* cb4 = (float4*)&xin[tb ^ 1][ov][0];   // 16B-aligned (144*ov)
            cb4[0] = f0; cb4[1] = f1; cb4[2] = f2;        // 3x STS.128
            if (t + 2 < NT) {                  // prefetch raw(t+2)
                uint32_t d = (uint32_t)__cvta_generic_to_shared(&raws[t & 1][ov][0]);
                const float* src = inp + ((size_t)vg * NT + (t + 2)) * 12;
                cpasync16(d, src); cpasync16(d + 16, src + 4); cpasync16(d + 32, src + 8);
                CP_COMMIT();
            }
        }
        __syncthreads();   // barrier 2: xs + cur(t+1) visible

        // ---- Phase C: lc / acc / spd (warps 0-1; no trailing barrier) ----
        if (tid < 4 * VB) {
            const int cv = tid >> 2, cq = tid & 3;
            const int vg = vbase0 + cv;
            float acc = s_headb[cq];
#pragma unroll
            for (int m = 0; m < 10; m++) acc = fmaf(xs[cv][m], s_head[m][cq], acc);
            if (cq < 3) {
                out[OUT_LC + ((size_t)vg * NT + t) * 3 + cq] = acc;
            } else {
                float a = fmaf(10.0f, acc, -6.0f);
                s_spd[cv] = fmaf(0.1f, a, s_spd[cv]);
            }
        }
        // C(t) reads xs / writes s_spd; B(t+1) writes xs / reads s_spd — ordered
        // by barrier 1 of step t+1. A(t+1) touches only xin buffers, disjoint.
    }

    __syncthreads();
    // ---- finals ----
    if (tid < VB) out[OUT_SPD + vbase0 + tid] = s_spd[tid];
    for (int i = tid; i < VB * UNITS; i += THREADS) {
        int v = i / UNITS, uu = i % UNITS;
        out[OUT_H + (size_t)(vbase0 + v) * UNITS + uu] = xin[NT & 1][v][12 + uu];
    }
    if (p == 0) {
#pragma unroll
        for (int vi = 0; vi < 4; vi++)
            out[OUT_C + (size_t)(vbase0 + v0 + vi) * UNITS + u] = c2[vi];
    }
}

extern "C" void kernel_launch(void* const* d_in, const int* in_sizes, int n_in,
                              void* d_out, int out_size) {
    const float* inp        = (const float*)d_in[0];
    const float* init_state = (const float*)d_in[1];
    const float* h0         = (const float*)d_in[2];
    const float* c0         = (const float*)d_in[3];
    const float* Wk         = (const float*)d_in[4];
    const float* Wr         = (const float*)d_in[5];
    const float* bzv        = (const float*)d_in[6];
    const float* d2w        = (const float*)d_in[7];
    const float* d2b        = (const float*)d_in[8];
    const float* lcw        = (const float*)d_in[9];
    const float* lcb        = (const float*)d_in[10];
    const float* d1w        = (const float*)d_in[11];
    const float* d1b        = (const float*)d_in[12];
    float* out = (float*)d_out;

    rnncf_kernel<<<BLOCKS, THREADS>>>(inp, init_state, h0, c0, Wk, Wr, bzv,
                                      d2w, d2b, lcw, lcb, d1w, d1b, out);
}